// round 15
// baseline (speedup 1.0000x reference)
#include <cuda_runtime.h>
#include <cuda_fp16.h>
#include <cstdint>

#define HW_ 262144            // 512*512
#define TILE 64
#define GRID 16384

// Fragment-linear fp16 weight images for mma.sync m16n8k16 B operand.
__device__ __align__(16) __half g_bf[3][65536];  // W1..W3 [kb(16)][n8pair(16)][lane(32)][8]
__device__ __align__(16) __half g_w0f[4096];     // W0 [1 kb][n8pair(16)][lane(32)][8], k<3 live
__device__ __align__(16) __half g_w4f[2048];     // W4 [kb(16)][lane(32)][2 x f16x2]
__device__ __align__(16) float4 g_c0f[64];       // layer0 bias frags [pair(16)][tg(4)]
__device__ __align__(16) float4 g_bsf[192];      // [l(3)][pair(16)][tg(4)]
__device__ float g_b4f[4];

// ---------------- prep: fp32 W -> fp16 fragment-linear + packed biases ----------------
__global__ void prep_kernel(const float* __restrict__ W0, const float* __restrict__ W1,
                            const float* __restrict__ W2, const float* __restrict__ W3,
                            const float* __restrict__ W4, const float* __restrict__ style,
                            const float* __restrict__ b0, const float* __restrict__ b1,
                            const float* __restrict__ b2, const float* __restrict__ b3,
                            const float* __restrict__ b4) {
  int t = blockIdx.x * blockDim.x + threadIdx.x;
  if (t < 196608) {
    int l = t >> 16, e = t & 65535;
    int k = e >> 8, n = e & 255;
    const float* W = (l == 0) ? W1 : (l == 1 ? W2 : W3);
    int kb = k >> 4, kr = k & 15;
    int n8 = n >> 3, g = n & 7;
    int tg = (kr >> 1) & 3;
    int lane = g * 4 + tg;
    int breg = kr >> 3, hs = kr & 1;
    int halfidx = (n8 & 1) * 4 + breg * 2 + hs;
    int dst = ((kb * 16 + (n8 >> 1)) * 32 + lane) * 8 + halfidx;
    g_bf[l][dst] = __float2half_rn(W[k * 256 + n]);
  } else if (t < 200704) {
    int e = t - 196608;                  // k(16) x n(256)
    int k = e >> 8, n = e & 255;
    int n8 = n >> 3, g = n & 7;
    int tg = (k >> 1) & 3;
    int lane = g * 4 + tg;
    int breg = k >> 3, hs = k & 1;
    int halfidx = (n8 & 1) * 4 + breg * 2 + hs;
    int dst = ((n8 >> 1) * 32 + lane) * 8 + halfidx;
    g_w0f[dst] = __float2half_rn(k < 3 ? W0[k * 256 + n] : 0.f);
  } else if (t < 202752) {
    int e = t - 200704;                  // kglob(256) x n(8)
    int kglob = e >> 3, n = e & 7;
    int kbG = kglob >> 4, kr = kglob & 15;
    int tg = (kr >> 1) & 3;
    int lane = n * 4 + tg;
    int breg = kr >> 3, hs = kr & 1;
    int dst = ((kbG * 32 + lane) * 2 + breg) * 2 + hs;
    g_w4f[dst] = __float2half_rn(n < 3 ? W4[kglob * 3 + n] : 0.f);
  } else if (t < 202816) {
    int e = t - 202752;                  // layer0 bias frag: jj(16) tg(4)
    int jj = e >> 2, tg = e & 3;
    int c = jj * 16 + tg * 2;
    float s0 = style[0], s1 = style[1], s2 = style[2];
    float4 v;
    v.x = b0[c]     + s0 * W0[768 + c]     + s1 * W0[1024 + c]     + s2 * W0[1280 + c];
    v.y = b0[c + 1] + s0 * W0[768 + c + 1] + s1 * W0[1024 + c + 1] + s2 * W0[1280 + c + 1];
    v.z = b0[c + 8] + s0 * W0[768 + c + 8] + s1 * W0[1024 + c + 8] + s2 * W0[1280 + c + 8];
    v.w = b0[c + 9] + s0 * W0[768 + c + 9] + s1 * W0[1024 + c + 9] + s2 * W0[1280 + c + 9];
    g_c0f[e] = v;
  } else if (t < 203008) {
    int e = t - 202816;                  // hidden bias frag: l(3) jj(16) tg(4)
    int l = e >> 6, r = e & 63;
    int jj = r >> 2, tg = r & 3;
    int c = jj * 16 + tg * 2;
    const float* B = (l == 0) ? b1 : (l == 1 ? b2 : b3);
    g_bsf[e] = make_float4(B[c], B[c + 1], B[c + 8], B[c + 9]);
  } else if (t < 203012) {
    int e = t - 203008;
    g_b4f[e] = (e < 3) ? b4[e] : 0.f;
  }
}

// ---------------- helpers ----------------
__device__ __forceinline__ uint32_t packh2(float lo, float hi) {
  uint32_t r;
  asm("cvt.rn.f16x2.f32 %0, %1, %2;" : "=f"(*(float*)&r) : "f"(hi), "f"(lo));
  return r;
}
__device__ __forceinline__ uint32_t tanh2(uint32_t p) {
  uint32_t r;
  asm("tanh.approx.f16x2 %0, %1;" : "=r"(r) : "r"(p));
  return r;
}
__device__ __forceinline__ uint32_t max0h2(uint32_t p) {
  uint32_t r;
  asm("max.f16x2 %0, %1, %2;" : "=r"(r) : "r"(p), "r"(0u));
  return r;
}
__device__ __forceinline__ void mma16816(float* c, const uint4& a, uint32_t b0, uint32_t b1) {
  asm volatile("mma.sync.aligned.m16n8k16.row.col.f32.f16.f16.f32 "
               "{%0,%1,%2,%3}, {%4,%5,%6,%7}, {%8,%9}, {%0,%1,%2,%3};"
               : "+f"(c[0]), "+f"(c[1]), "+f"(c[2]), "+f"(c[3])
               : "r"(a.x), "r"(a.y), "r"(a.z), "r"(a.w), "r"(b0), "r"(b1));
}
__device__ __forceinline__ uint4 tanh_frag(const float* e, const float* o) {
  uint4 f;
  f.x = tanh2(packh2(e[0], e[1])); f.y = tanh2(packh2(e[2], e[3]));
  f.z = tanh2(packh2(o[0], o[1])); f.w = tanh2(packh2(o[2], o[3]));
  return f;
}

// ---------------- main: 128 thr, 2 CTAs/SM, cascaded 3-stage drain ----------------
__global__ void __launch_bounds__(128, 2) cnilut_main(
    const float* __restrict__ x, float* __restrict__ out) {
  __shared__ uint4 sA[2 * 2048];   // 64KB: two A buffers; sA[2048..] also final partials

  int tid = threadIdx.x, wid = tid >> 5, lane = tid & 31;
  int g = lane >> 2, tg = lane & 3;

  // ---- early LDGs: layer0 B fragments + own pixels ----
  uint4 bf0[4];
  #pragma unroll
  for (int j = 0; j < 4; j++)
    bf0[j] = __ldg((const uint4*)g_w0f + (wid * 4 + j) * 32 + lane);

  int p0 = blockIdx.x * TILE + wid * 16 + g;
  int img = p0 >> 18, hw = p0 & (HW_ - 1);
  const float* xb = x + (size_t)img * 3 * HW_ + hw;
  float xv[2][3];
  #pragma unroll
  for (int c = 0; c < 3; c++) { xv[0][c] = xb[(size_t)c * HW_]; xv[1][c] = xb[(size_t)c * HW_ + 8]; }

  // layer0 A fragments (k = tg*2, tg*2+1; only k<3 live)
  uint4 af0[4];
  #pragma unroll
  for (int i = 0; i < 4; i++) {
    uint32_t ax = 0, ay = 0;
    if (tg < 2) {
      int rp = blockIdx.x * TILE + i * 16 + g;
      int im2 = rp >> 18, hw2 = rp & (HW_ - 1);
      const float* xq = x + (size_t)im2 * 3 * HW_ + hw2;
      float va  = (tg == 0) ? xq[0]        : xq[2 * (size_t)HW_];
      float vb  = (tg == 0) ? xq[HW_]      : 0.f;
      float va2 = (tg == 0) ? xq[8]        : xq[2 * (size_t)HW_ + 8];
      float vb2 = (tg == 0) ? xq[HW_ + 8]  : 0.f;
      ax = packh2(va, vb);
      ay = packh2(va2, vb2);
    }
    af0[i] = make_uint4(ax, ay, 0u, 0u);
  }

  float acc[4][8][4];

  // ---- layer 0 via MMA: relu(x.W0 + c0) -> sA buf0 ----
  {
    #pragma unroll
    for (int jj = 0; jj < 4; jj++) {
      float4 bv = __ldg(&g_c0f[(wid * 4 + jj) * 4 + tg]);
      #pragma unroll
      for (int i = 0; i < 4; i++) {
        acc[i][2 * jj][0] = bv.x; acc[i][2 * jj][1] = bv.y;
        acc[i][2 * jj][2] = bv.x; acc[i][2 * jj][3] = bv.y;
        acc[i][2 * jj + 1][0] = bv.z; acc[i][2 * jj + 1][1] = bv.w;
        acc[i][2 * jj + 1][2] = bv.z; acc[i][2 * jj + 1][3] = bv.w;
      }
    }
    #pragma unroll
    for (int i = 0; i < 4; i++)
      #pragma unroll
      for (int j = 0; j < 4; j++) {
        mma16816(acc[i][2 * j],     af0[i], bf0[j].x, bf0[j].y);
        mma16816(acc[i][2 * j + 1], af0[i], bf0[j].z, bf0[j].w);
      }
  }

  // prefetch layer-1 first B fragments (pairs wid*4, wid*4+1; kb 0,1)
  uint4 bfp[2][2];
  {
    const uint4* gB = (const uint4*)g_bf[0];
    #pragma unroll
    for (int kb = 0; kb < 2; kb++)
      #pragma unroll
      for (int j = 0; j < 2; j++)
        bfp[kb][j] = __ldg(gB + (kb * 16 + wid * 4 + j) * 32 + lane);
  }

  // layer0 epilogue: relu + pack -> buf0
  #pragma unroll
  for (int jj = 0; jj < 4; jj++) {
    #pragma unroll
    for (int i = 0; i < 4; i++) {
      float* e = acc[i][2 * jj];
      float* o = acc[i][2 * jj + 1];
      uint32_t a0 = max0h2(packh2(e[0], e[1]));
      uint32_t a1 = max0h2(packh2(e[2], e[3]));
      uint32_t a2 = max0h2(packh2(o[0], o[1]));
      uint32_t a3 = max0h2(packh2(o[2], o[3]));
      sA[(i * 16 + (wid * 4 + jj)) * 32 + lane] = make_uint4(a0, a1, a2, a3);
    }
  }
  __syncthreads();

  // ---- 3 hidden layers: double-buffered A, cascaded sub-tiles N=32+16+16 ----
  float res[4][4];

  #pragma unroll 1
  for (int l = 0; l < 3; l++) {
    const uint4* rd = sA + (l & 1) * 2048;
    uint4* wr = sA + ((l + 1) & 1) * 2048;
    const uint4* gB = (const uint4*)g_bf[l];

    // prefetch pair2 kb0,1 (consumed a full loop later)
    uint4 bfp2[2];
    #pragma unroll
    for (int kb = 0; kb < 2; kb++)
      bfp2[kb] = __ldg(gB + (kb * 16 + wid * 4 + 2) * 32 + lane);

    // ---- bias init pairs 0,1 ----
    #pragma unroll
    for (int jj = 0; jj < 2; jj++) {
      float4 bv = __ldg(&g_bsf[l * 64 + (wid * 4 + jj) * 4 + tg]);
      #pragma unroll
      for (int i = 0; i < 4; i++) {
        acc[i][2 * jj][0] = bv.x; acc[i][2 * jj][1] = bv.y;
        acc[i][2 * jj][2] = bv.x; acc[i][2 * jj][3] = bv.y;
        acc[i][2 * jj + 1][0] = bv.z; acc[i][2 * jj + 1][1] = bv.w;
        acc[i][2 * jj + 1][2] = bv.z; acc[i][2 * jj + 1][3] = bv.w;
      }
    }
    // ---- loop A: pairs 0,1 ----
    {
      uint4 bfr[3][2];
      #pragma unroll
      for (int j = 0; j < 2; j++) { bfr[0][j] = bfp[0][j]; bfr[1][j] = bfp[1][j]; }
      #pragma unroll
      for (int kb = 0; kb < 16; kb++) {
        int cur = kb % 3;
        if (kb < 14) {
          int nxt = (kb + 2) % 3;
          #pragma unroll
          for (int j = 0; j < 2; j++)
            bfr[nxt][j] = __ldg(gB + ((kb + 2) * 16 + wid * 4 + j) * 32 + lane);
        }
        uint4 af[4];
        #pragma unroll
        for (int i = 0; i < 4; i++) af[i] = rd[(i * 16 + kb) * 32 + lane];
        #pragma unroll
        for (int i = 0; i < 4; i++)
          #pragma unroll
          for (int j = 0; j < 2; j++) {
            mma16816(acc[i][2 * j],     af[i], bfr[cur][j].x, bfr[cur][j].y);
            mma16816(acc[i][2 * j + 1], af[i], bfr[cur][j].z, bfr[cur][j].w);
          }
      }
    }

    // ---- bias init pair 2; res zero for l==2 (drains start in loop B) ----
    {
      float4 bv = __ldg(&g_bsf[l * 64 + (wid * 4 + 2) * 4 + tg]);
      #pragma unroll
      for (int i = 0; i < 4; i++) {
        acc[i][4][0] = bv.x; acc[i][4][1] = bv.y; acc[i][4][2] = bv.x; acc[i][4][3] = bv.y;
        acc[i][5][0] = bv.z; acc[i][5][1] = bv.w; acc[i][5][2] = bv.z; acc[i][5][3] = bv.w;
      }
    }
    if (l == 2) {
      #pragma unroll
      for (int i = 0; i < 4; i++)
        #pragma unroll
        for (int r = 0; r < 4; r++) res[i][r] = 0.f;
    }

    // prefetch pair3 kb0,1 (consumed a full loop later)
    uint4 bfp3[2];
    #pragma unroll
    for (int kb = 0; kb < 2; kb++)
      bfp3[kb] = __ldg(gB + (kb * 16 + wid * 4 + 3) * 32 + lane);

    // ---- loop B: pair 2, drain pairs 0,1 (1 frag per 2 kb) ----
    {
      uint4 bfr2[3];
      bfr2[0] = bfp2[0]; bfr2[1] = bfp2[1];
      #pragma unroll
      for (int kb = 0; kb < 16; kb++) {
        int cur = kb % 3;
        if (kb < 14)
          bfr2[(kb + 2) % 3] = __ldg(gB + ((kb + 2) * 16 + wid * 4 + 2) * 32 + lane);
        uint4 af[4];
        #pragma unroll
        for (int i = 0; i < 4; i++) af[i] = rd[(i * 16 + kb) * 32 + lane];
        #pragma unroll
        for (int i = 0; i < 4; i++) {
          mma16816(acc[i][4], af[i], bfr2[cur].x, bfr2[cur].y);
          mma16816(acc[i][5], af[i], bfr2[cur].z, bfr2[cur].w);
        }
        if (kb & 1) {   // 8 drains: (i, jj) over i0..3 x jj0..1
          int ei = kb >> 1, i = ei >> 1, jj = ei & 1;
          uint4 f = tanh_frag(acc[i][2 * jj], acc[i][2 * jj + 1]);
          if (l < 2) {
            wr[(i * 16 + (wid * 4 + jj)) * 32 + lane] = f;
          } else {
            uint2 wv = __ldg((const uint2*)g_w4f + (wid * 4 + jj) * 32 + lane);
            mma16816(res[i], f, wv.x, wv.y);
          }
        }
      }
    }

    // ---- bias init pair 3 ----
    {
      float4 bv = __ldg(&g_bsf[l * 64 + (wid * 4 + 3) * 4 + tg]);
      #pragma unroll
      for (int i = 0; i < 4; i++) {
        acc[i][6][0] = bv.x; acc[i][6][1] = bv.y; acc[i][6][2] = bv.x; acc[i][6][3] = bv.y;
        acc[i][7][0] = bv.z; acc[i][7][1] = bv.w; acc[i][7][2] = bv.z; acc[i][7][3] = bv.w;
      }
    }

    // ---- loop C: pair 3, drain pair 2 (1 frag per 4 kb) ----
    {
      uint4 bfr3[3];
      bfr3[0] = bfp3[0]; bfr3[1] = bfp3[1];
      #pragma unroll
      for (int kb = 0; kb < 16; kb++) {
        int cur = kb % 3;
        if (kb < 14)
          bfr3[(kb + 2) % 3] = __ldg(gB + ((kb + 2) * 16 + wid * 4 + 3) * 32 + lane);
        uint4 af[4];
        #pragma unroll
        for (int i = 0; i < 4; i++) af[i] = rd[(i * 16 + kb) * 32 + lane];
        #pragma unroll
        for (int i = 0; i < 4; i++) {
          mma16816(acc[i][6], af[i], bfr3[cur].x, bfr3[cur].y);
          mma16816(acc[i][7], af[i], bfr3[cur].z, bfr3[cur].w);
        }
        if ((kb & 3) == 3) {   // 4 drains: pair 2, i = kb>>2
          int i = kb >> 2;
          uint4 f = tanh_frag(acc[i][4], acc[i][5]);
          if (l < 2) {
            wr[(i * 16 + (wid * 4 + 2)) * 32 + lane] = f;
          } else {
            uint2 wv = __ldg((const uint2*)g_w4f + (wid * 4 + 2) * 32 + lane);
            mma16816(res[i], f, wv.x, wv.y);
          }
        }
      }
    }

    // ---- next-layer B prefetch (pairs 0,1; kb 0,1) before exposed drain ----
    if (l < 2) {
      const uint4* gBn = (const uint4*)g_bf[l + 1];
      #pragma unroll
      for (int kb = 0; kb < 2; kb++)
        #pragma unroll
        for (int j = 0; j < 2; j++)
          bfp[kb][j] = __ldg(gBn + (kb * 16 + wid * 4 + j) * 32 + lane);
    }

    // ---- exposed drain: pair 3 only (4 frags) ----
    #pragma unroll
    for (int i = 0; i < 4; i++) {
      uint4 f = tanh_frag(acc[i][6], acc[i][7]);
      if (l < 2) {
        wr[(i * 16 + (wid * 4 + 3)) * 32 + lane] = f;
      } else {
        uint2 wv = __ldg((const uint2*)g_w4f + (wid * 4 + 3) * 32 + lane);
        mma16816(res[i], f, wv.x, wv.y);
      }
    }
    if (l == 2) {
      // partials -> buf1 (idle during l=2): P[(mblk*4 + wid)*32 + lane]
      float4* P = (float4*)(sA + 2048);
      #pragma unroll
      for (int i = 0; i < 4; i++)
        P[(i * 4 + wid) * 32 + lane] = make_float4(res[i][0], res[i][1], res[i][2], res[i][3]);
    }
    __syncthreads();
  }

  // ---- cross-warp reduce + residual + clip + store ----
  {
    const float4* P = (const float4*)(sA + 2048);
    float4 q0 = P[(wid * 4 + 0) * 32 + lane];
    float4 q1 = P[(wid * 4 + 1) * 32 + lane];
    float4 q2 = P[(wid * 4 + 2) * 32 + lane];
    float4 q3 = P[(wid * 4 + 3) * 32 + lane];
    float r0 = q0.x + q1.x + q2.x + q3.x;
    float r1 = q0.y + q1.y + q2.y + q3.y;
    float r2 = q0.z + q1.z + q2.z + q3.z;
    float r3 = q0.w + q1.w + q2.w + q3.w;
    float* ob = out + (size_t)img * 3 * HW_ + hw;
    if (tg == 0) {
      float bb0 = __ldg(&g_b4f[0]), bb1 = __ldg(&g_b4f[1]);
      ob[0]        = fminf(fmaxf(xv[0][0] + r0 + bb0, 0.f), 1.f);
      ob[HW_]      = fminf(fmaxf(xv[0][1] + r1 + bb1, 0.f), 1.f);
      ob[8]        = fminf(fmaxf(xv[1][0] + r2 + bb0, 0.f), 1.f);
      ob[HW_ + 8]  = fminf(fmaxf(xv[1][1] + r3 + bb1, 0.f), 1.f);
    } else if (tg == 1) {
      float bb2 = __ldg(&g_b4f[2]);
      ob[2 * (size_t)HW_]     = fminf(fmaxf(xv[0][2] + r0 + bb2, 0.f), 1.f);
      ob[2 * (size_t)HW_ + 8] = fminf(fmaxf(xv[1][2] + r2 + bb2, 0.f), 1.f);
    }
  }
}

extern "C" void kernel_launch(void* const* d_in, const int* in_sizes, int n_in,
                              void* d_out, int out_size) {
  const float* x     = (const float*)d_in[0];
  const float* style = (const float*)d_in[1];
  const float* W0    = (const float*)d_in[2];
  const float* b0    = (const float*)d_in[3];
  const float* W1    = (const float*)d_in[4];
  const float* b1    = (const float*)d_in[5];
  const float* W2    = (const float*)d_in[6];
  const float* b2    = (const float*)d_in[7];
  const float* W3    = (const float*)d_in[8];
  const float* b3    = (const float*)d_in[9];
  const float* W4    = (const float*)d_in[10];
  const float* b4    = (const float*)d_in[11];
  float* out = (float*)d_out;

  prep_kernel<<<794, 256>>>(W0, W1, W2, W3, W4, style, b0, b1, b2, b3, b4);
  cnilut_main<<<GRID, 128>>>(x, out);
}

// round 16
// speedup vs baseline: 1.0721x; 1.0721x over previous
#include <cuda_runtime.h>
#include <cuda_fp16.h>
#include <cstdint>

#define HW_ 262144            // 512*512
#define TILE 64
#define TPC 4                 // tiles per CTA
#define GRID 4096

// Fragment-linear fp16 weight images for mma.sync m16n8k16 B operand.
__device__ __align__(16) __half g_bf[3][65536];  // W1..W3 [kb(16)][n8pair(16)][lane(32)][8]
__device__ __align__(16) __half g_w0f[4096];     // W0 [1 kb][n8pair(16)][lane(32)][8], k<3 live
__device__ __align__(16) __half g_w4f[2048];     // W4 [kb(16)][lane(32)][2 x f16x2]
__device__ __align__(16) float4 g_c0f[64];       // layer0 bias frags [pair(16)][tg(4)]
__device__ __align__(16) float4 g_bsf[192];      // [l(3)][pair(16)][tg(4)]
__device__ float g_b4f[4];

// ---------------- prep: fp32 W -> fp16 fragment-linear + packed biases ----------------
__global__ void prep_kernel(const float* __restrict__ W0, const float* __restrict__ W1,
                            const float* __restrict__ W2, const float* __restrict__ W3,
                            const float* __restrict__ W4, const float* __restrict__ style,
                            const float* __restrict__ b0, const float* __restrict__ b1,
                            const float* __restrict__ b2, const float* __restrict__ b3,
                            const float* __restrict__ b4) {
  int t = blockIdx.x * blockDim.x + threadIdx.x;
  if (t < 196608) {
    int l = t >> 16, e = t & 65535;
    int k = e >> 8, n = e & 255;
    const float* W = (l == 0) ? W1 : (l == 1 ? W2 : W3);
    int kb = k >> 4, kr = k & 15;
    int n8 = n >> 3, g = n & 7;
    int tg = (kr >> 1) & 3;
    int lane = g * 4 + tg;
    int breg = kr >> 3, hs = kr & 1;
    int halfidx = (n8 & 1) * 4 + breg * 2 + hs;
    int dst = ((kb * 16 + (n8 >> 1)) * 32 + lane) * 8 + halfidx;
    g_bf[l][dst] = __float2half_rn(W[k * 256 + n]);
  } else if (t < 200704) {
    int e = t - 196608;                  // k(16) x n(256)
    int k = e >> 8, n = e & 255;
    int n8 = n >> 3, g = n & 7;
    int tg = (k >> 1) & 3;
    int lane = g * 4 + tg;
    int breg = k >> 3, hs = k & 1;
    int halfidx = (n8 & 1) * 4 + breg * 2 + hs;
    int dst = ((n8 >> 1) * 32 + lane) * 8 + halfidx;
    g_w0f[dst] = __float2half_rn(k < 3 ? W0[k * 256 + n] : 0.f);
  } else if (t < 202752) {
    int e = t - 200704;                  // kglob(256) x n(8)
    int kglob = e >> 3, n = e & 7;
    int kbG = kglob >> 4, kr = kglob & 15;
    int tg = (kr >> 1) & 3;
    int lane = n * 4 + tg;
    int breg = kr >> 3, hs = kr & 1;
    int dst = ((kbG * 32 + lane) * 2 + breg) * 2 + hs;
    g_w4f[dst] = __float2half_rn(n < 3 ? W4[kglob * 3 + n] : 0.f);
  } else if (t < 202816) {
    int e = t - 202752;                  // layer0 bias frag: jj(16) tg(4)
    int jj = e >> 2, tg = e & 3;
    int c = jj * 16 + tg * 2;
    float s0 = style[0], s1 = style[1], s2 = style[2];
    float4 v;
    v.x = b0[c]     + s0 * W0[768 + c]     + s1 * W0[1024 + c]     + s2 * W0[1280 + c];
    v.y = b0[c + 1] + s0 * W0[768 + c + 1] + s1 * W0[1024 + c + 1] + s2 * W0[1280 + c + 1];
    v.z = b0[c + 8] + s0 * W0[768 + c + 8] + s1 * W0[1024 + c + 8] + s2 * W0[1280 + c + 8];
    v.w = b0[c + 9] + s0 * W0[768 + c + 9] + s1 * W0[1024 + c + 9] + s2 * W0[1280 + c + 9];
    g_c0f[e] = v;
  } else if (t < 203008) {
    int e = t - 202816;                  // hidden bias frag: l(3) jj(16) tg(4)
    int l = e >> 6, r = e & 63;
    int jj = r >> 2, tg = r & 3;
    int c = jj * 16 + tg * 2;
    const float* B = (l == 0) ? b1 : (l == 1 ? b2 : b3);
    g_bsf[e] = make_float4(B[c], B[c + 1], B[c + 8], B[c + 9]);
  } else if (t < 203012) {
    int e = t - 203008;
    g_b4f[e] = (e < 3) ? b4[e] : 0.f;
  }
}

// ---------------- helpers ----------------
__device__ __forceinline__ uint32_t packh2(float lo, float hi) {
  uint32_t r;
  asm("cvt.rn.f16x2.f32 %0, %1, %2;" : "=f"(*(float*)&r) : "f"(hi), "f"(lo));
  return r;
}
__device__ __forceinline__ uint32_t tanh2(uint32_t p) {
  uint32_t r;
  asm("tanh.approx.f16x2 %0, %1;" : "=r"(r) : "r"(p));
  return r;
}
__device__ __forceinline__ uint32_t max0h2(uint32_t p) {
  uint32_t r;
  asm("max.f16x2 %0, %1, %2;" : "=r"(r) : "r"(p), "r"(0u));
  return r;
}
__device__ __forceinline__ void mma16816(float* c, const uint4& a, uint32_t b0, uint32_t b1) {
  asm volatile("mma.sync.aligned.m16n8k16.row.col.f32.f16.f16.f32 "
               "{%0,%1,%2,%3}, {%4,%5,%6,%7}, {%8,%9}, {%0,%1,%2,%3};"
               : "+f"(c[0]), "+f"(c[1]), "+f"(c[2]), "+f"(c[3])
               : "r"(a.x), "r"(a.y), "r"(a.z), "r"(a.w), "r"(b0), "r"(b1));
}
__device__ __forceinline__ uint4 tanh_frag(const float* e, const float* o) {
  uint4 f;
  f.x = tanh2(packh2(e[0], e[1])); f.y = tanh2(packh2(e[2], e[3]));
  f.z = tanh2(packh2(o[0], o[1])); f.w = tanh2(packh2(o[2], o[3]));
  return f;
}
__device__ __forceinline__ void load_tile_x(int tile, int g, int tg,
                                            float xv[2][3], uint4 af0[4],
                                            const float* __restrict__ x) {
  int p0 = tile * TILE + 0 * 16 + g;   // xv uses warp-specific row below; caller fixes
  (void)p0;
  #pragma unroll
  for (int i = 0; i < 4; i++) {
    uint32_t ax = 0, ay = 0;
    if (tg < 2) {
      int rp = tile * TILE + i * 16 + g;
      int im2 = rp >> 18, hw2 = rp & (HW_ - 1);
      const float* xq = x + (size_t)im2 * 3 * HW_ + hw2;
      float va  = (tg == 0) ? __ldg(xq)           : __ldg(xq + 2 * (size_t)HW_);
      float vb  = (tg == 0) ? __ldg(xq + HW_)     : 0.f;
      float va2 = (tg == 0) ? __ldg(xq + 8)       : __ldg(xq + 2 * (size_t)HW_ + 8);
      float vb2 = (tg == 0) ? __ldg(xq + HW_ + 8) : 0.f;
      ax = packh2(va, vb);
      ay = packh2(va2, vb2);
    }
    af0[i] = make_uint4(ax, ay, 0u, 0u);
  }
}

// ---------------- main: 128 thr, 2 CTAs/SM, R14 body x 4 tiles per CTA ----------------
__global__ void __launch_bounds__(128, 2) cnilut_main(
    const float* __restrict__ x, float* __restrict__ out) {
  __shared__ uint4 sA[2 * 2048];   // 64KB: two A buffers; buf1 also final partials

  int tid = threadIdx.x, wid = tid >> 5, lane = tid & 31;
  int g = lane >> 2, tg = lane & 3;

  float xv[2][3];
  uint4 af0[4];
  float nxv[2][3];
  uint4 naf0[4];

  // ---- tile 0 pixel loads ----
  {
    int tile = blockIdx.x * TPC;
    int p0 = tile * TILE + wid * 16 + g;
    int im = p0 >> 18, h = p0 & (HW_ - 1);
    const float* xb = x + (size_t)im * 3 * HW_ + h;
    #pragma unroll
    for (int c = 0; c < 3; c++) { xv[0][c] = xb[(size_t)c * HW_]; xv[1][c] = xb[(size_t)c * HW_ + 8]; }
    load_tile_x(tile, g, tg, xv, af0, x);
  }
  // layer-1 first B fragments (pairs wid*4, wid*4+1; kb 0,1)
  uint4 bfp[2][2];
  {
    const uint4* gB = (const uint4*)g_bf[0];
    #pragma unroll
    for (int kb = 0; kb < 2; kb++)
      #pragma unroll
      for (int j = 0; j < 2; j++)
        bfp[kb][j] = __ldg(gB + (kb * 16 + wid * 4 + j) * 32 + lane);
  }

  float acc[4][8][4];
  float res[4][4];

  #pragma unroll 1
  for (int tt = 0; tt < TPC; tt++) {
    int tile = blockIdx.x * TPC + tt;
    int p0 = tile * TILE + wid * 16 + g;
    int img = p0 >> 18, hw = p0 & (HW_ - 1);

    // ---- layer 0 via MMA: relu(x.W0 + c0) -> sA buf0 ----
    {
      uint4 bf0[4];
      #pragma unroll
      for (int j = 0; j < 4; j++)
        bf0[j] = __ldg((const uint4*)g_w0f + (wid * 4 + j) * 32 + lane);
      #pragma unroll
      for (int jj = 0; jj < 4; jj++) {
        float4 bv = __ldg(&g_c0f[(wid * 4 + jj) * 4 + tg]);
        #pragma unroll
        for (int i = 0; i < 4; i++) {
          acc[i][2 * jj][0] = bv.x; acc[i][2 * jj][1] = bv.y;
          acc[i][2 * jj][2] = bv.x; acc[i][2 * jj][3] = bv.y;
          acc[i][2 * jj + 1][0] = bv.z; acc[i][2 * jj + 1][1] = bv.w;
          acc[i][2 * jj + 1][2] = bv.z; acc[i][2 * jj + 1][3] = bv.w;
        }
      }
      #pragma unroll
      for (int i = 0; i < 4; i++)
        #pragma unroll
        for (int j = 0; j < 4; j++) {
          mma16816(acc[i][2 * j],     af0[i], bf0[j].x, bf0[j].y);
          mma16816(acc[i][2 * j + 1], af0[i], bf0[j].z, bf0[j].w);
        }
      // relu + pack -> buf0
      #pragma unroll
      for (int jj = 0; jj < 4; jj++) {
        #pragma unroll
        for (int i = 0; i < 4; i++) {
          float* e = acc[i][2 * jj];
          float* o = acc[i][2 * jj + 1];
          uint32_t a0 = max0h2(packh2(e[0], e[1]));
          uint32_t a1 = max0h2(packh2(e[2], e[3]));
          uint32_t a2 = max0h2(packh2(o[0], o[1]));
          uint32_t a3 = max0h2(packh2(o[2], o[3]));
          sA[(i * 16 + (wid * 4 + jj)) * 32 + lane] = make_uint4(a0, a1, a2, a3);
        }
      }
    }
    __syncthreads();

    // ---- 3 hidden layers: double-buffered A, sub-tiled (N=32+32) epilogue ----
    #pragma unroll 1
    for (int l = 0; l < 3; l++) {
      const uint4* rd = sA + (l & 1) * 2048;
      uint4* wr = sA + ((l + 1) & 1) * 2048;
      const uint4* gB = (const uint4*)g_bf[l];

      // ---- sub-tile A (pairs wid*4, wid*4+1): bias init + K loop ----
      #pragma unroll
      for (int jj = 0; jj < 2; jj++) {
        float4 bv = __ldg(&g_bsf[l * 64 + (wid * 4 + jj) * 4 + tg]);
        #pragma unroll
        for (int i = 0; i < 4; i++) {
          acc[i][2 * jj][0] = bv.x; acc[i][2 * jj][1] = bv.y;
          acc[i][2 * jj][2] = bv.x; acc[i][2 * jj][3] = bv.y;
          acc[i][2 * jj + 1][0] = bv.z; acc[i][2 * jj + 1][1] = bv.w;
          acc[i][2 * jj + 1][2] = bv.z; acc[i][2 * jj + 1][3] = bv.w;
        }
      }
      {
        uint4 bfr[3][2];
        #pragma unroll
        for (int j = 0; j < 2; j++) { bfr[0][j] = bfp[0][j]; bfr[1][j] = bfp[1][j]; }
        #pragma unroll
        for (int kb = 0; kb < 16; kb++) {
          int cur = kb % 3;
          if (kb < 14) {
            int nxt = (kb + 2) % 3;
            #pragma unroll
            for (int j = 0; j < 2; j++)
              bfr[nxt][j] = __ldg(gB + ((kb + 2) * 16 + wid * 4 + j) * 32 + lane);
          }
          uint4 af[4];
          #pragma unroll
          for (int i = 0; i < 4; i++) af[i] = rd[(i * 16 + kb) * 32 + lane];
          #pragma unroll
          for (int i = 0; i < 4; i++)
            #pragma unroll
            for (int j = 0; j < 2; j++) {
              mma16816(acc[i][2 * j],     af[i], bfr[cur][j].x, bfr[cur][j].y);
              mma16816(acc[i][2 * j + 1], af[i], bfr[cur][j].z, bfr[cur][j].w);
            }
        }
      }

      // ---- sub-tile B (pairs wid*4+2, +3): bias init, K loop w/ interleaved subA drain ----
      #pragma unroll
      for (int jj = 2; jj < 4; jj++) {
        float4 bv = __ldg(&g_bsf[l * 64 + (wid * 4 + jj) * 4 + tg]);
        #pragma unroll
        for (int i = 0; i < 4; i++) {
          acc[i][2 * jj][0] = bv.x; acc[i][2 * jj][1] = bv.y;
          acc[i][2 * jj][2] = bv.x; acc[i][2 * jj][3] = bv.y;
          acc[i][2 * jj + 1][0] = bv.z; acc[i][2 * jj + 1][1] = bv.w;
          acc[i][2 * jj + 1][2] = bv.z; acc[i][2 * jj + 1][3] = bv.w;
        }
      }
      if (l == 2) {
        #pragma unroll
        for (int i = 0; i < 4; i++)
          #pragma unroll
          for (int r = 0; r < 4; r++) res[i][r] = 0.f;
      }
      {
        uint4 bfr[3][2];
        #pragma unroll
        for (int kb = 0; kb < 2; kb++)
          #pragma unroll
          for (int j = 0; j < 2; j++)
            bfr[kb][j] = __ldg(gB + (kb * 16 + wid * 4 + 2 + j) * 32 + lane);
        #pragma unroll
        for (int kb = 0; kb < 16; kb++) {
          int cur = kb % 3;
          if (kb < 14) {
            int nxt = (kb + 2) % 3;
            #pragma unroll
            for (int j = 0; j < 2; j++)
              bfr[nxt][j] = __ldg(gB + ((kb + 2) * 16 + wid * 4 + 2 + j) * 32 + lane);
          }
          uint4 af[4];
          #pragma unroll
          for (int i = 0; i < 4; i++) af[i] = rd[(i * 16 + kb) * 32 + lane];
          #pragma unroll
          for (int i = 0; i < 4; i++)
            #pragma unroll
            for (int j = 0; j < 2; j++) {
              mma16816(acc[i][2 * (j + 2)],     af[i], bfr[cur][j].x, bfr[cur][j].y);
              mma16816(acc[i][2 * (j + 2) + 1], af[i], bfr[cur][j].z, bfr[cur][j].w);
            }
          if (kb & 1) {   // drain one subA frag per 2 kb (8 total)
            int ei = kb >> 1, i = ei >> 1, jj = ei & 1;
            uint4 f = tanh_frag(acc[i][2 * jj], acc[i][2 * jj + 1]);
            if (l < 2) {
              wr[(i * 16 + (wid * 4 + jj)) * 32 + lane] = f;
            } else {
              uint2 wv = __ldg((const uint2*)g_w4f + (wid * 4 + jj) * 32 + lane);
              mma16816(res[i], f, wv.x, wv.y);
            }
          }
        }
      }

      // ---- next B prefetch (next layer, or next tile's layer-1 when l==2) ----
      {
        const uint4* gBn = (const uint4*)((l < 2) ? g_bf[l + 1] : g_bf[0]);
        #pragma unroll
        for (int kb = 0; kb < 2; kb++)
          #pragma unroll
          for (int j = 0; j < 2; j++)
            bfp[kb][j] = __ldg(gBn + (kb * 16 + wid * 4 + j) * 32 + lane);
      }
      // ---- next-tile pixel prefetch during l==2 (subA acc regs are dead) ----
      if (l == 2 && tt < TPC - 1) {
        int ntile = tile + 1;
        int np = ntile * TILE + wid * 16 + g;
        int nim = np >> 18, nh = np & (HW_ - 1);
        const float* nxb = x + (size_t)nim * 3 * HW_ + nh;
        #pragma unroll
        for (int c = 0; c < 3; c++) { nxv[0][c] = __ldg(nxb + (size_t)c * HW_); nxv[1][c] = __ldg(nxb + (size_t)c * HW_ + 8); }
        load_tile_x(ntile, g, tg, nxv, naf0, x);
      }

      // ---- exposed drain of sub-tile B (jj 2,3) ----
      #pragma unroll
      for (int ei = 0; ei < 8; ei++) {
        int i = ei >> 1, jj = 2 + (ei & 1);
        uint4 f = tanh_frag(acc[i][2 * jj], acc[i][2 * jj + 1]);
        if (l < 2) {
          wr[(i * 16 + (wid * 4 + jj)) * 32 + lane] = f;
        } else {
          uint2 wv = __ldg((const uint2*)g_w4f + (wid * 4 + jj) * 32 + lane);
          mma16816(res[i], f, wv.x, wv.y);
        }
      }
      if (l == 2) {
        float4* P = (float4*)(sA + 2048);
        #pragma unroll
        for (int i = 0; i < 4; i++)
          P[(i * 4 + wid) * 32 + lane] = make_float4(res[i][0], res[i][1], res[i][2], res[i][3]);
      }
      __syncthreads();
    }

    // ---- cross-warp reduce + residual + clip + store ----
    {
      const float4* P = (const float4*)(sA + 2048);
      float4 q0 = P[(wid * 4 + 0) * 32 + lane];
      float4 q1 = P[(wid * 4 + 1) * 32 + lane];
      float4 q2 = P[(wid * 4 + 2) * 32 + lane];
      float4 q3 = P[(wid * 4 + 3) * 32 + lane];
      float r0 = q0.x + q1.x + q2.x + q3.x;
      float r1 = q0.y + q1.y + q2.y + q3.y;
      float r2 = q0.z + q1.z + q2.z + q3.z;
      float r3 = q0.w + q1.w + q2.w + q3.w;
      float* ob = out + (size_t)img * 3 * HW_ + hw;
      if (tg == 0) {
        float bb0 = __ldg(&g_b4f[0]), bb1 = __ldg(&g_b4f[1]);
        ob[0]        = fminf(fmaxf(xv[0][0] + r0 + bb0, 0.f), 1.f);
        ob[HW_]      = fminf(fmaxf(xv[0][1] + r1 + bb1, 0.f), 1.f);
        ob[8]        = fminf(fmaxf(xv[1][0] + r2 + bb0, 0.f), 1.f);
        ob[HW_ + 8]  = fminf(fmaxf(xv[1][1] + r3 + bb1, 0.f), 1.f);
      } else if (tg == 1) {
        float bb2 = __ldg(&g_b4f[2]);
        ob[2 * (size_t)HW_]     = fminf(fmaxf(xv[0][2] + r0 + bb2, 0.f), 1.f);
        ob[2 * (size_t)HW_ + 8] = fminf(fmaxf(xv[1][2] + r2 + bb2, 0.f), 1.f);
      }
    }

    // ---- rotate prefetched pixels in ----
    if (tt < TPC - 1) {
      #pragma unroll
      for (int c = 0; c < 3; c++) { xv[0][c] = nxv[0][c]; xv[1][c] = nxv[1][c]; }
      #pragma unroll
      for (int i = 0; i < 4; i++) af0[i] = naf0[i];
      __syncthreads();   // partials buf1 fully read before next tile's l=0 writes it
    }
  }
}

extern "C" void kernel_launch(void* const* d_in, const int* in_sizes, int n_in,
                              void* d_out, int out_size) {
  const float* x     = (const float*)d_in[0];
  const float* style = (const float*)d_in[1];
  const float* W0    = (const float*)d_in[2];
  const float* b0    = (const float*)d_in[3];
  const float* W1    = (const float*)d_in[4];
  const float* b1    = (const float*)d_in[5];
  const float* W2    = (const float*)d_in[6];
  const float* b2    = (const float*)d_in[7];
  const float* W3    = (const float*)d_in[8];
  const float* b3    = (const float*)d_in[9];
  const float* W4    = (const float*)d_in[10];
  const float* b4    = (const float*)d_in[11];
  float* out = (float*)d_out;

  prep_kernel<<<794, 256>>>(W0, W1, W2, W3, W4, style, b0, b1, b2, b3, b4);
  cnilut_main<<<GRID, 128>>>(x, out);
}